// round 17
// baseline (speedup 1.0000x reference)
#include <cuda_runtime.h>

// IDCT (DCT-III), B=4096 rows, N=4096. Makhoul + Hermitian-packed 2048-pt
// complex inverse FFT per row. 2048 = 8 * 8 * 8 * 4, 256 threads, 8 pts/thread:
//   stage1 radix-8 fused with Z build (x read directly from global, j-pairing)
//   stage2 radix-8, IN-PLACE (read all to regs, sync, write back)
//   stage3 radix-8, IN-PLACE
//   stage4 radix-4 (trivial twiddles) fused with output permutation
// SMEM: ONE 2048-float2 buffer (16 KB), XOR-swizzled (conflict-free for
// stride-8/64/512 writes and stride-256 reads; hand-checked per bank-pair).
// bound-5 (51-reg budget) -> 5 CTAs x 8 warps = 40 warps/SM.

#define NN 4096
#define MM 2048
#define THREADS 256
#define SW(m) ((m) ^ (((m) >> 4) & 15))

__device__ __forceinline__ float2 cadd(float2 a, float2 b) { return make_float2(a.x + b.x, a.y + b.y); }
__device__ __forceinline__ float2 csub(float2 a, float2 b) { return make_float2(a.x - b.x, a.y - b.y); }
__device__ __forceinline__ float2 cmul(float2 a, float2 b) {
    return make_float2(fmaf(a.x, b.x, -a.y * b.y), fmaf(a.x, b.y, a.y * b.x));
}
__device__ __forceinline__ float2 csqr(float2 a) {
    return make_float2(fmaf(a.x, a.x, -a.y * a.y), 2.0f * a.x * a.y);
}

// Inverse DFT-8 (+j convention).
__device__ __forceinline__ void idft8(const float2 a[8], float2 X[8]) {
    const float C = 0.70710678118654752f;
    float2 p0 = cadd(a[0], a[4]), m0 = csub(a[0], a[4]);
    float2 q0 = cadd(a[2], a[6]);
    float2 r0 = make_float2(-(a[2].y - a[6].y), a[2].x - a[6].x);
    float2 E0 = cadd(p0, q0), E1 = cadd(m0, r0), E2 = csub(p0, q0), E3 = csub(m0, r0);
    float2 p1 = cadd(a[1], a[5]), m1 = csub(a[1], a[5]);
    float2 q1 = cadd(a[3], a[7]);
    float2 r1 = make_float2(-(a[3].y - a[7].y), a[3].x - a[7].x);
    float2 O0 = cadd(p1, q1), O1 = cadd(m1, r1), O2 = csub(p1, q1), O3 = csub(m1, r1);
    float2 T1 = make_float2(C * (O1.x - O1.y), C * (O1.x + O1.y));
    float2 T2 = make_float2(-O2.y, O2.x);
    float2 T3 = make_float2(-C * (O3.x + O3.y), C * (O3.x - O3.y));
    X[0] = cadd(E0, O0); X[4] = csub(E0, O0);
    X[1] = cadd(E1, T1); X[5] = csub(E1, T1);
    X[2] = cadd(E2, T2); X[6] = csub(E2, T2);
    X[3] = cadd(E3, T3); X[7] = csub(E3, T3);
}

// Twiddle tree (depth <= 3 from w1, all products independent) + swizzled store:
// out[SW(base + m*S)] = w1^m * X_m, m = 0..7.
__device__ __forceinline__ void tw_store8(float2* __restrict__ out, const float2 X[8],
                                          float2 w1, int base, int S) {
    float2 w2 = csqr(w1);
    float2 w4 = csqr(w2);
    float2 w3 = cmul(w1, w2);
    float2 w5 = cmul(w1, w4);
    float2 w6 = cmul(w2, w4);
    float2 w7 = cmul(w3, w4);
    out[SW(base)]         = X[0];
    out[SW(base + S)]     = cmul(w1, X[1]);
    out[SW(base + 2 * S)] = cmul(w2, X[2]);
    out[SW(base + 3 * S)] = cmul(w3, X[3]);
    out[SW(base + 4 * S)] = cmul(w4, X[4]);
    out[SW(base + 5 * S)] = cmul(w5, X[5]);
    out[SW(base + 6 * S)] = cmul(w6, X[6]);
    out[SW(base + 7 * S)] = cmul(w7, X[7]);
}

// One Z element: x quartet, expk entry E, rotation W (e^{j*2pi*k/4096} or j*that).
__device__ __forceinline__ float2 z_elem(float xk, float xnk, float xmk, float xmpk,
                                         float2 E, float2 W, float C8) {
    float c1 = E.x, s1 = -E.y;
    // e^{j*pi*(2048-k)/8192} = e^{j*pi/4} * conj(e^{j*pi*k/8192})
    float c2 = C8 * (c1 + s1), s2 = C8 * (c1 - s1);
    float2 Vk = make_float2(fmaf(xk, c1, xnk * s1), fmaf(xk, s1, -xnk * c1));
    float2 Vm = make_float2(fmaf(xmk, c2, xmpk * s2), fmaf(xmk, s2, -xmpk * c2));
    float2 P = make_float2(Vk.x + Vm.x, Vk.y - Vm.y);   // V_k + conj(V_{M-k})
    float2 Q = make_float2(Vk.x - Vm.x, Vk.y + Vm.y);   // V_k - conj(V_{M-k})
    return make_float2(P.x - W.y * Q.x - W.x * Q.y,
                       P.y + W.x * Q.x - W.y * Q.y);
}

__global__ __launch_bounds__(THREADS, 5)
void idct_kernel(const float* __restrict__ x,
                 const float2* __restrict__ expk,
                 float* __restrict__ y) {
    extern __shared__ float2 buf[];   // 2048 float2, in-place via syncs

    const int tid = threadIdx.x;
    const float* xr = x + (size_t)blockIdx.x * NN;
    const float C8 = 0.70710678118654752f;

    // Stage twiddle bases (exact loads; flip(expk[m]) = e^{j*pi*m/8192}):
    //   stage1: W_2048^tid   = flip(expk[8*tid])    (8*255 = 2040 < 4096)
    //   stage2: W_2048^{8p2} = flip(expk[64*p2])    (broadcast in groups of 8)
    //   stage3: W_2048^{64p3}= flip(expk[512*p3])   (warp-broadcast)
    const int p2 = tid >> 3, q2 = tid & 7;
    const int p3 = tid >> 6, q3 = tid & 63;
    float2 Ew1 = __ldg(&expk[8 * tid]);
    float2 Ew2 = __ldg(&expk[64 * p2]);
    float2 Ew3 = __ldg(&expk[512 * p3]);

    // ---- Z build + radix-8 stage 1 (S=1, p=tid, inputs k = tid + 256n) ----
    // Pair k and k+1024 (= n, n+4): one W = e^{j*2pi*k/4096} serves both (W' = j*W).
    {
        float2 Z[8];
#pragma unroll
        for (int i = 0; i < 4; i++) {
            int k  = tid + i * THREADS;   // [0, 1024)
            int k2 = k + 1024;            // [1024, 2048)

            float xk   = xr[k];
            float xnk  = (k == 0) ? 0.0f : xr[NN - k];
            float xmk  = xr[MM - k];
            float xmpk = xr[MM + k];
            float2 E1 = __ldg(&expk[k]);
            float2 W  = csqr(csqr(make_float2(E1.x, -E1.y)));   // e^{j*2pi*k/4096}
            Z[i] = z_elem(xk, xnk, xmk, xmpk, E1, W, C8);

            float yk   = xr[k2];
            float ynk  = xr[NN - k2];
            float ymk  = xr[MM - k2];
            float ympk = xr[MM + k2];
            float2 F1 = __ldg(&expk[k2]);
            float2 Wj = make_float2(-W.y, W.x);                  // j*W, exact
            Z[i + 4] = z_elem(yk, ynk, ymk, ympk, F1, Wj, C8);
        }
        float2 X[8];
        idft8(Z, X);
        tw_store8(buf, X, make_float2(Ew1.x, -Ew1.y), 8 * tid, 1);
    }
    __syncthreads();

    // ---- radix-8 stage 2 (S=8): in-place (read all -> sync -> write) ----
    {
        float2 a[8], X[8];
#pragma unroll
        for (int n = 0; n < 8; n++) a[n] = buf[SW(tid + 256 * n)];
        idft8(a, X);
        __syncthreads();
        tw_store8(buf, X, make_float2(Ew2.x, -Ew2.y), q2 + 64 * p2, 8);
    }
    __syncthreads();

    // ---- radix-8 stage 3 (S=64): in-place ----
    {
        float2 a[8], X[8];
#pragma unroll
        for (int n = 0; n < 8; n++) a[n] = buf[SW(tid + 256 * n)];
        idft8(a, X);
        __syncthreads();
        tw_store8(buf, X, make_float2(Ew3.x, -Ew3.y), q3 + 512 * p3, 64);
    }
    __syncthreads();

    // ---- radix-4 stage 4 (S=512, p=0 -> trivial twiddles) fused with output ----
    // Thread handles butterflies b1=tid, b2=511-tid: partner of z_{b+512m}
    // is z_{2047-(b+512m)} = z_{(511-b)+512(3-m)} -> thread-local.
    {
        const int b1 = tid, b2 = 511 - tid;
        float2 z1[4], z2[4];
        {
            float2 a0 = buf[SW(b1)],        a1 = buf[SW(b1 + 512)];
            float2 a2 = buf[SW(b1 + 1024)], a3 = buf[SW(b1 + 1536)];
            float2 s02 = cadd(a0, a2), d02 = csub(a0, a2);
            float2 s13 = cadd(a1, a3);
            float2 jd13 = make_float2(-(a1.y - a3.y), a1.x - a3.x);
            z1[0] = cadd(s02, s13); z1[1] = cadd(d02, jd13);
            z1[2] = csub(s02, s13); z1[3] = csub(d02, jd13);
        }
        {
            float2 a0 = buf[SW(b2)],        a1 = buf[SW(b2 + 512)];
            float2 a2 = buf[SW(b2 + 1024)], a3 = buf[SW(b2 + 1536)];
            float2 s02 = cadd(a0, a2), d02 = csub(a0, a2);
            float2 s13 = cadd(a1, a3);
            float2 jd13 = make_float2(-(a1.y - a3.y), a1.x - a3.x);
            z2[0] = cadd(s02, s13); z2[1] = cadd(d02, jd13);
            z2[2] = csub(s02, s13); z2[3] = csub(d02, jd13);
        }
        // y[4s..4s+3] = {Re z_s, Im z_{2047-s}, Im z_s, Re z_{2047-s}}
        float4* yr = (float4*)(y + (size_t)blockIdx.x * NN);
        yr[b1]       = make_float4(z1[0].x, z2[3].y, z1[0].y, z2[3].x);
        yr[b1 + 512] = make_float4(z1[1].x, z2[2].y, z1[1].y, z2[2].x);
        yr[b2]       = make_float4(z2[0].x, z1[3].y, z2[0].y, z1[3].x);
        yr[b2 + 512] = make_float4(z2[1].x, z1[2].y, z2[1].y, z1[2].x);
    }
}

extern "C" void kernel_launch(void* const* d_in, const int* in_sizes, int n_in,
                              void* d_out, int out_size) {
    const float*  x    = (const float*)d_in[0];
    const float2* expk = (const float2*)d_in[1];
    float*        y    = (float*)d_out;

    int rows = in_sizes[0] / NN;                 // 4096
    size_t smem_bytes = MM * sizeof(float2);     // 16 KB, single in-place buffer
    idct_kernel<<<rows, THREADS, smem_bytes>>>(x, expk, y);
}